// round 12
// baseline (speedup 1.0000x reference)
#include <cuda_runtime.h>
#include <math.h>
#include <stdint.h>

#define B_    64
#define T_    1000
#define D_    512
#define V_    29
#define L_    200
#define S_    401            // 2*L + 1
#define CBLANK 28
#define LOG2E 1.44269504088896340736f
#define LN2   0.69314718055994530942f
#define ESENT (-(1 << 29))   // integer-exponent sentinel ("-inf")

typedef unsigned long long u64;

// ---------------- device scratch (no allocations allowed) ----------------
__device__ float d_lp[(long)B_ * T_ * V_];   // LINEAR probs p[b][t][v], 7.4 MB
__device__ float d_loss[B_];

__device__ __forceinline__ float ex2f(float x){ float r; asm("ex2.approx.f32 %0, %1;" : "=f"(r) : "f"(x)); return r; }
__device__ __forceinline__ float lg2f(float x){ float r; asm("lg2.approx.f32 %0, %1;" : "=f"(r) : "f"(x)); return r; }

#define FMA2(d, a, b) asm("fma.rn.f32x2 %0, %1, %2, %0;" : "+l"(d) : "l"(a), "l"(b))

// =====================================================================
// Kernel 1: logits = F @ W + b, softmax, write LINEAR probs to d_lp.
// (R8/R10 proven 2-stage structure.) 256 threads, BM=256 rows/block,
// tile 8 rows x 4 cols, FFMA2 over k-pairs; W resident transposed.
// =====================================================================
#define BM2 256
#define WT_STRIDE 516
#define SMEM_GEMM_BYTES 132608

extern __shared__ char smem_dyn[];

__global__ __launch_bounds__(256, 1) void gemm_sm_kernel(
    const float* __restrict__ F, const float* __restrict__ W,
    const float* __restrict__ bias)
{
    float* fbuf = (float*)smem_dyn;
    float* wT   = (float*)(smem_dyn + 65536);
    float* csh  = (float*)(smem_dyn + 131584);
    float* lbuf = fbuf;                         // epilogue reuse

    const int tid = threadIdx.x;
    const long rowBase = (long)blockIdx.x * BM2;
    const uint32_t fsh = (uint32_t)__cvta_generic_to_shared(fbuf);

    auto prefetch = [&](int kci, int st) {
        const uint32_t sbase = fsh + st * 32768u;
#pragma unroll
        for (int m = 0; m < 8; m++) {
            const int q  = tid + 256 * m;
            const int r  = q >> 3;
            const int kq = q & 7;
            const float* src = F + (rowBase + r) * D_ + kci * 32 + kq * 4;
            const uint32_t dst = sbase + (uint32_t)((r * 32 + ((kq ^ ((r >> 3) & 7)) << 2)) * 4);
            asm volatile("cp.async.ca.shared.global [%0], [%1], 16;" :: "r"(dst), "l"(src));
        }
    };

    prefetch(0, 0);
    asm volatile("cp.async.commit_group;");

    for (int idx = tid; idx < 512 * 32; idx += 256) {
        const int k = idx >> 5, c = idx & 31;
        wT[c * WT_STRIDE + k] = (c < V_) ? W[(long)k * V_ + c] : 0.f;
    }

    const int rg = tid >> 3;
    const int cg = tid & 7;
    const int fkey = (rg & 7) << 2;

    float bv[4];
#pragma unroll
    for (int j = 0; j < 4; j++) { int c = cg + 8 * j; bv[j] = (c < V_) ? bias[c] : 0.f; }

    u64 acc[8][4];
#pragma unroll
    for (int i = 0; i < 8; i++)
#pragma unroll
        for (int j = 0; j < 4; j++) acc[i][j] = 0ull;

    for (int kci = 0; kci < 16; kci++) {
        if (kci < 15) prefetch(kci + 1, (kci + 1) & 1);
        asm volatile("cp.async.commit_group;");
        asm volatile("cp.async.wait_group 1;");
        __syncthreads();

        const float* fstage = fbuf + (kci & 1) * 8192;
        const float* wbase  = wT + kci * 32;
#pragma unroll
        for (int kq = 0; kq < 8; kq++) {
            ulonglong2 f[8], w4[4];
#pragma unroll
            for (int i = 0; i < 8; i++)
                f[i] = *reinterpret_cast<const ulonglong2*>(
                    fstage + (rg * 8 + i) * 32 + ((kq << 2) ^ fkey));
#pragma unroll
            for (int j = 0; j < 4; j++)
                w4[j] = *reinterpret_cast<const ulonglong2*>(
                    wbase + (cg + 8 * j) * WT_STRIDE + kq * 4);
#pragma unroll
            for (int i = 0; i < 8; i++)
#pragma unroll
                for (int j = 0; j < 4; j++) FMA2(acc[i][j], f[i].x, w4[j].x);
#pragma unroll
            for (int i = 0; i < 8; i++)
#pragma unroll
                for (int j = 0; j < 4; j++) FMA2(acc[i][j], f[i].y, w4[j].y);
        }
        __syncthreads();
    }

#pragma unroll
    for (int i = 0; i < 8; i++)
#pragma unroll
        for (int j = 0; j < 4; j++) {
            const float lo = __uint_as_float((unsigned)(acc[i][j] & 0xffffffffull));
            const float hi = __uint_as_float((unsigned)(acc[i][j] >> 32));
            lbuf[(rg * 8 + i) * 33 + (cg + 8 * j)] = lo + hi + bv[j];
        }
    __syncthreads();

    {
        const float* r = &lbuf[tid * 33];
        float m = r[0];
#pragma unroll
        for (int v = 1; v < V_; v++) m = fmaxf(m, r[v]);
        float sum = 0.f;
#pragma unroll
        for (int v = 0; v < V_; v++) sum += ex2f((r[v] - m) * LOG2E);
        csh[tid] = m * LOG2E + lg2f(sum);
    }
    __syncthreads();

    // coalesced write of LINEAR probabilities
    float* outp = d_lp + rowBase * V_;
    for (int i = tid; i < BM2 * V_; i += 256) {
        const int row = i / V_;
        const int v   = i - row * V_;
        outp[i] = ex2f(lbuf[row * 33 + v] * LOG2E - csh[row]);
    }
}

// =====================================================================
// Kernel 2: CTC alpha recursion, EXACT LINEAR (mantissa, int-exponent),
// PAIRED STATES, zero MUFU. One block per batch, 224 threads (7 warps);
// thread i owns pair (blank 2i, label 2i+1) as {m in [1,2), E int} x 2.
// Neighbor data = ONE float4 LDS (pair i-1). Both updates depend only
// on step-(t-1) values (ILP=2, pure 4-cycle ALU/FMA chains).
// One cheap 7-warp barrier per step; 4-deep LDG prefetch x 2 streams.
// =====================================================================
__global__ __launch_bounds__(224) void ctc_kernel(
    const int* __restrict__ labels, const int* __restrict__ flens,
    const int* __restrict__ llens)
{
    __shared__ float4 pbuf[2][226];     // [.][i+1] = {mb, Eb, ml, El} of pair i
    __shared__ int    lab_sh[L_];

    const int b    = blockIdx.x;
    const int tid  = threadIdx.x;
    const int flen = flens[b];
    const int llen = llens[b];

    for (int i = tid; i < L_; i += 224) lab_sh[i] = labels[b * L_ + i];
    if (tid == 0) {
        const float4 pad = make_float4(1.f, __int_as_float(ESENT),
                                       1.f, __int_as_float(ESENT));
        pbuf[0][0] = pad; pbuf[1][0] = pad;
    }
    __syncthreads();

    const int i = tid;                  // pair index; i >= 200 = dummy
    int   ext   = CBLANK;
    bool  skip1 = false;
    if (i < 200) {
        ext   = lab_sh[i];
        skip1 = (i >= 1) && (ext != lab_sh[i - 1]);
    }

    const float* lpb = d_lp + (long)b * T_ * V_;

    // t = 0 init: only pair 0 is live
    float mb = 1.f, ml = 1.f;
    int   Eb = ESENT, El = ESENT;
    if (i == 0) {
        const unsigned b0 = __float_as_uint(lpb[CBLANK]);
        Eb = (int)(b0 >> 23) - 127;
        mb = __uint_as_float((b0 & 0x007fffffu) | 0x3f800000u);
        const unsigned b1 = __float_as_uint(lpb[ext]);
        El = (int)(b1 >> 23) - 127;
        ml = __uint_as_float((b1 & 0x007fffffu) | 0x3f800000u);
    }
    pbuf[0][i + 1] = make_float4(mb, __int_as_float(Eb), ml, __int_as_float(El));

    // 4-deep prefetch, two streams (blank col broadcast, label col)
    float pB0 = lpb[1 * V_ + CBLANK], pE0 = lpb[1 * V_ + ext];
    float pB1 = lpb[2 * V_ + CBLANK], pE1 = lpb[2 * V_ + ext];
    float pB2 = lpb[3 * V_ + CBLANK], pE2 = lpb[3 * V_ + ext];
    float pB3 = lpb[4 * V_ + CBLANK], pE3 = lpb[4 * V_ + ext];
    __syncthreads();

    int cur = 0;
    int t = 1;

#define MKSCALE(d) __uint_as_float((unsigned)max((d) + 127, 0) << 23)

#define CTC_STEP(PB, PE) do {                                                    \
    const float4 nb = pbuf[cur][i];          /* pair i-1: {m,E}x2 */             \
    const float n1m = nb.z;                                                      \
    const int   n1E = __float_as_int(nb.w);  /* alpha[2i-1] */                   \
    /* blank state 2i: self + neighbor label */                                  \
    const int   EmB = max(Eb, n1E);                                              \
    const float sB  = fmaf(mb, MKSCALE(Eb - EmB), n1m * MKSCALE(n1E - EmB));     \
    const float vB  = PB * sB;                                                   \
    /* label state 2i+1: self + own blank + (skip) neighbor label */             \
    const int   E2  = skip1 ? n1E : ESENT;                                       \
    const int   EmL = max(El, max(Eb, E2));                                      \
    const float sL  = fmaf(ml, MKSCALE(El - EmL),                                \
                      fmaf(mb, MKSCALE(Eb - EmL), n1m * MKSCALE(E2 - EmL)));     \
    const float vL  = PE * sL;                                                   \
    const unsigned bB = __float_as_uint(vB);                                     \
    Eb = EmB + (int)(bB >> 23) - 127;                                            \
    mb = __uint_as_float((bB & 0x007fffffu) | 0x3f800000u);                      \
    const unsigned bL = __float_as_uint(vL);                                     \
    El = EmL + (int)(bL >> 23) - 127;                                            \
    ml = __uint_as_float((bL & 0x007fffffu) | 0x3f800000u);                      \
    pbuf[cur ^ 1][i + 1] = make_float4(mb, __int_as_float(Eb),                   \
                                       ml, __int_as_float(El));                  \
    cur ^= 1;                                                                    \
    const int tn = min(t + 4, T_ - 1) * V_;                                      \
    PB = lpb[tn + CBLANK]; PE = lpb[tn + ext];                                   \
    __syncthreads();                                                             \
    t++;                                                                         \
} while (0)

    while (t + 3 < flen) {
        CTC_STEP(pB0, pE0); CTC_STEP(pB1, pE1);
        CTC_STEP(pB2, pE2); CTC_STEP(pB3, pE3);
    }
    while (t < flen) {
        CTC_STEP(pB0, pE0);
        pB0 = pB1; pE0 = pE1; pB1 = pB2; pE1 = pE2; pB2 = pB3; pE2 = pE3;
    }
#undef CTC_STEP
#undef MKSCALE

    if (tid == 0) {
        const float4 vA = pbuf[cur][llen + 1];   // pair llen: blank 2*llen
        const float4 vB = pbuf[cur][llen];       // pair llen-1: label 2*llen-1
        const float l1 = (float)__float_as_int(vA.y) + lg2f(vA.x);
        const float l2 = (float)__float_as_int(vB.w) + lg2f(vB.z);
        const float mx = fmaxf(l1, l2), mn = fminf(l1, l2);
        const float ls = mx + lg2f(1.0f + ex2f(mn - mx));
        const float nll = -ls * LN2;
        d_loss[b] = (nll < 5e8f) ? nll / (float)llen : 0.f;
    }
}

// =====================================================================
// Kernel 3: deterministic fixed-order mean of 64 losses
// =====================================================================
__global__ void reduce_kernel(float* __restrict__ out)
{
    const int lane = threadIdx.x;
    float v = d_loss[lane] + d_loss[lane + 32];
#pragma unroll
    for (int o = 16; o > 0; o >>= 1) v += __shfl_down_sync(0xffffffffu, v, o);
    if (lane == 0) out[0] = v * (1.f / (float)B_);
}

// =====================================================================
extern "C" void kernel_launch(void* const* d_in, const int* in_sizes, int n_in,
                              void* d_out, int out_size)
{
    (void)in_sizes; (void)n_in; (void)out_size;
    const float* F      = (const float*)d_in[0];
    const float* W      = (const float*)d_in[1];
    const float* bias   = (const float*)d_in[2];
    const int*   labels = (const int*)d_in[3];
    const int*   flens  = (const int*)d_in[4];
    const int*   llens  = (const int*)d_in[5];
    float* out = (float*)d_out;

    cudaFuncSetAttribute(gemm_sm_kernel,
                         cudaFuncAttributeMaxDynamicSharedMemorySize, SMEM_GEMM_BYTES);

    gemm_sm_kernel<<<(B_ * T_) / BM2, 256, SMEM_GEMM_BYTES>>>(F, W, bias);
    ctc_kernel<<<B_, 224>>>(labels, flens, llens);
    reduce_kernel<<<1, 32>>>(out);
}